// round 9
// baseline (speedup 1.0000x reference)
#include <cuda_runtime.h>
#include <cuda_bf16.h>
#include <mma.h>
using namespace nvcuda;
typedef __nv_bfloat16 bf16;

constexpr int BATCH = 32;
constexpr int SEQT  = 96;
constexpr int DIN   = 256;
constexpr int HID   = 512;
constexpr int NHEAD = 4;
constexpr int VOCAB = 32000;
constexpr int NG    = 4 * HID;           // 2048
constexpr int LIN0  = DIN + NHEAD*HID;   // 2304  (x_t | cvec)
constexpr int K0    = LIN0 + HID;        // 2816  (+ h0prev)
constexpr int K1    = 2 * HID;           // 1024  (h0n | h1prev)
constexpr int ZK    = (1 + NHEAD) * HID; // 2560

constexpr int GRID = 148;
constexpr int NTH  = 256;
constexpr int F0   = K0 / 16;    // 176 frags (22/warp)
constexpr int F0A  = LIN0 / 16;  // 144 frags from xc part
constexpr int F1   = K1 / 16;    // 64 frags (8/warp)
constexpr int FQ   = HID / 16;   // 32 frags (4/warp)

// smem layout for k_recur (dynamic)
constexpr int W0S_OFF = 0;                       // 16 x 2816 bf16 = 90112
constexpr int W1S_OFF = 90112;                   // 16 x 1024 bf16 = 32768
constexpr int WQS_OFF = 122880;                  // 16 x 512  bf16 = 16384
constexpr int RED_OFF = 139264;                  // 4096 floats = 16384
constexpr int SMEM_RECUR = 155648;

// Wo conversion hidden in idle blocks: 20 blocks x 384 slots
constexpr long CVT_N = (long)VOCAB * ZK / 2;     // 40,960,000 bf16x2
constexpr long CVT_CHUNK = 5376;                 // 20*384*5376 >= CVT_N

// ---------------- device scratch ----------------
__device__ __align__(256) float g_buf[BATCH][SEQT+1][HID];
__device__ __align__(256) float g_P  [BATCH][SEQT+1][HID];
__device__ __align__(256) float g_q  [BATCH][HID];
__device__ __align__(256) float g_c0[BATCH][HID], g_c1[BATCH][HID];
__device__ __align__(256) float g_bias0p[NG], g_bias1p[NG];
__device__ __align__(256) bf16 g_h1b[BATCH][HID];       // qp input
__device__ __align__(256) bf16 g_xc0b[BATCH][LIN0];     // [x_t | cvec]
__device__ __align__(256) bf16 g_h0prev[2][BATCH][HID]; // parity double-buffer
__device__ __align__(256) bf16 g_h0nb[BATCH][HID];      // layer-1 input (this step)
__device__ __align__(256) bf16 g_h1prev[2][BATCH][HID];
__device__ __align__(256) bf16 g_W0p[NG][K0];           // gate-interleaved (po = h*4+g)
__device__ __align__(256) bf16 g_W1p[NG][K1];
__device__ __align__(256) bf16 g_Wqpb[2*HID][HID];
__device__ __align__(256) bf16 g_Zb [BATCH*SEQT][ZK];
__device__ __align__(256) bf16 g_Wob[VOCAB][ZK];
__device__ unsigned g_barCnt;
__device__ unsigned g_barPhase;

__device__ __forceinline__ float sigf(float x) { return 1.0f / (1.0f + expf(-x)); }

// ---------------- grid barrier (all GRID blocks resident) ----------------
__device__ __forceinline__ void gbar() {
    __syncthreads();
    if (threadIdx.x == 0) {
        __threadfence();
        unsigned old = atomicAdd(&g_barCnt, 1u);
        unsigned target = old / GRID + 1u;
        if (old % GRID == GRID - 1u) {
            atomicExch(&g_barPhase, target);
        } else {
            const volatile unsigned* vp = &g_barPhase;
            while (*vp < target) { }
        }
        __threadfence();
    }
    __syncthreads();
}

// ---------------- setup: pack (gate-interleaved) + convert weights, zero state ----
__global__ void k_setup(const float* __restrict__ W_ih0, const float* __restrict__ W_hh0,
                        const float* __restrict__ b_ih0, const float* __restrict__ b_hh0,
                        const float* __restrict__ W_ih1, const float* __restrict__ W_hh1,
                        const float* __restrict__ b_ih1, const float* __restrict__ b_hh1,
                        const float* __restrict__ Wa1) {
    if (blockIdx.x == 0 && threadIdx.x == 0) { g_barCnt = 0u; g_barPhase = 0u; }
    long i      = (long)blockIdx.x * blockDim.x + threadIdx.x;
    long stride = (long)gridDim.x * blockDim.x;
    const long n0 = (long)NG * K0;            // W0p
    const long n1 = n0 + (long)NG * K1;       // W1p
    const long n2 = n1 + (long)2*HID*HID;     // Wqpb
    const long n3 = n2 + NG;                  // bias0p
    const long n4 = n3 + NG;                  // bias1p
    const long n5 = n4 + (long)3*BATCH*HID;   // fp32 zeros: c0,c1,buf[.,0,.]
    const long n6 = n5 + (long)5*BATCH*HID;   // bf16 zeros: h1b, h0prev x2, h1prev x2
    for (long idx = i; idx < n6; idx += stride) {
        if (idx < n0) {
            long po = idx / K0, k = idx % K0;
            long h = po >> 2, gt = po & 3;
            long orig = gt * HID + h;
            float v = (k < LIN0) ? W_ih0[orig*LIN0 + k] : W_hh0[orig*HID + (k - LIN0)];
            g_W0p[po][k] = __float2bfloat16(v);
        } else if (idx < n1) {
            long r = idx - n0; long po = r / K1, k = r % K1;
            long h = po >> 2, gt = po & 3;
            long orig = gt * HID + h;
            float v = (k < HID) ? W_ih1[orig*HID + k] : W_hh1[orig*HID + (k - HID)];
            g_W1p[po][k] = __float2bfloat16(v);
        } else if (idx < n2) {
            long r = idx - n1; long n = r / HID, k = r % HID;
            float v = (n < HID) ? Wa1[n*(2*HID) + k] : Wa1[(n-HID)*(2*HID) + HID + k];
            g_Wqpb[n][k] = __float2bfloat16(v);
        } else if (idx < n3) {
            long po = idx - n2;
            long h = po >> 2, gt = po & 3;
            long orig = gt * HID + h;
            g_bias0p[po] = b_ih0[orig] + b_hh0[orig];
        } else if (idx < n4) {
            long po = idx - n3;
            long h = po >> 2, gt = po & 3;
            long orig = gt * HID + h;
            g_bias1p[po] = b_ih1[orig] + b_hh1[orig];
        } else if (idx < n5) {
            long r = idx - n4; int which = (int)(r / (BATCH*HID));
            long o = r % (BATCH*HID); long b = o / HID, h = o % HID;
            if (which == 0) g_c0[b][h] = 0.f;
            else if (which == 1) g_c1[b][h] = 0.f;
            else g_buf[b][0][h] = 0.f;
        } else {
            long r = idx - n5; int which = (int)(r / (BATCH*HID));
            long o = r % (BATCH*HID); long b = o / HID, h = o % HID;
            bf16 z = __float2bfloat16(0.f);
            switch (which) {
                case 0: g_h1b[b][h] = z; break;
                case 1: g_h0prev[0][b][h] = z; break;
                case 2: g_h0prev[1][b][h] = z; break;
                case 3: g_h1prev[0][b][h] = z; break;
                default: g_h1prev[1][b][h] = z; break;
            }
        }
    }
}

// idle blocks convert Wo fp32 -> bf16, one chunk per barrier slot
__device__ __forceinline__ void cvt_slot(const float* __restrict__ Wo, int slot, int cb) {
    long base = ((long)slot * 20 + cb) * CVT_CHUNK;
    const float2* src = (const float2*)Wo;
    __nv_bfloat162* dst = (__nv_bfloat162*)&g_Wob[0][0];
    long end = base + CVT_CHUNK; if (end > CVT_N) end = CVT_N;
    for (long i = base + threadIdx.x; i < end; i += NTH)
        dst[i] = __float22bfloat162_rn(src[i]);
}

// ---------------- persistent recurrence ----------------
__global__ void __launch_bounds__(NTH) k_recur(const float* __restrict__ inputs,
                                               const float* __restrict__ Wa2,
                                               const float* __restrict__ ba1,
                                               const float* __restrict__ ba2,
                                               const float* __restrict__ Wo) {
    extern __shared__ char smem[];
    bf16*  w0s  = (bf16*)(smem + W0S_OFF);
    bf16*  w1s  = (bf16*)(smem + W1S_OFF);
    bf16*  wqs  = (bf16*)(smem + WQS_OFF);
    float* sred = (float*)(smem + RED_OFF);   // 4096 floats; attn aliases this

    const int bid = blockIdx.x, tid = threadIdx.x;
    const int warp = tid >> 5, lane = tid & 31;

    // ---- preload this block's weight slices into smem (once) ----
    if (bid < 128) {
        const uint4* s0 = (const uint4*)&g_W0p[bid*16][0];
        uint4* d0 = (uint4*)w0s;
        for (int i = tid; i < 16*K0/8; i += NTH) d0[i] = s0[i];
        const uint4* s1 = (const uint4*)&g_W1p[bid*16][0];
        uint4* d1 = (uint4*)w1s;
        for (int i = tid; i < 16*K1/8; i += NTH) d1[i] = s1[i];
        if (bid < 64) {
            const uint4* sq = (const uint4*)&g_Wqpb[bid*16][0];
            uint4* dq = (uint4*)wqs;
            for (int i = tid; i < 16*HID/8; i += NTH) dq[i] = sq[i];
        }
    }
    __syncthreads();

    for (int t = 0; t < SEQT; t++) {
        const int par = t & 1;

        // ===== stage 1: qp = h1b @ Wqpb^T (blocks 0..63, 16 cols each) =====
        if (bid < 64) {
            wmma::fragment<wmma::accumulator,16,16,16,float> c0f, c1f;
            wmma::fill_fragment(c0f, 0.f); wmma::fill_fragment(c1f, 0.f);
#pragma unroll
            for (int ff = 0; ff < FQ/8; ff++) {
                int f = warp*(FQ/8) + ff;
                wmma::fragment<wmma::matrix_a,16,16,16,bf16,wmma::row_major> a0, a1;
                wmma::fragment<wmma::matrix_b,16,16,16,bf16,wmma::col_major> bfr;
                const bf16* Ap = &g_h1b[0][0] + f*16;
                wmma::load_matrix_sync(a0, Ap, HID);
                wmma::load_matrix_sync(a1, Ap + 16*HID, HID);
                wmma::load_matrix_sync(bfr, wqs + f*16, HID);
                wmma::mma_sync(c0f, a0, bfr, c0f);
                wmma::mma_sync(c1f, a1, bfr, c1f);
            }
            wmma::store_matrix_sync(sred + warp*512,       c0f, 16, wmma::mem_row_major);
            wmma::store_matrix_sync(sred + warp*512 + 256, c1f, 16, wmma::mem_row_major);
            __syncthreads();
            int n0 = bid * 16;
            for (int e = tid; e < 512; e += NTH) {
                float s = 0.f;
#pragma unroll
                for (int w = 0; w < 8; w++) s += sred[w*512 + e];
                int b = e >> 4, n = n0 + (e & 15);
                if (n < HID) g_q[b][n] = s + ba1[n];
                else         g_P[b][t][n - HID] = s;
            }
        } else if (bid >= 128) cvt_slot(Wo, t*4 + 0, bid - 128);
        gbar();

        // ===== stage 2: attention (blocks 0..31 = batch) =====
        if (bid < BATCH) {
            int b = bid;
            float* sq  = sred;          // 512
            float* sW2 = sred + 512;    // 2048
            float* ss  = sred + 2560;   // up to 384
            for (int ho = tid; ho < HID; ho += NTH) sq[ho] = g_q[b][ho];
            for (int idx = tid; idx < NHEAD*HID; idx += NTH) sW2[idx] = Wa2[idx];
            __syncthreads();

            for (int j = warp; j <= t; j += 8) {
                float a0 = 0.f, a1 = 0.f, a2 = 0.f, a3 = 0.f;
                const float* Pj = &g_P[b][j][0];
                for (int ho = lane; ho < HID; ho += 32) {
                    float r = fmaxf(sq[ho] + Pj[ho], 0.f);
                    a0 += r * sW2[ho];
                    a1 += r * sW2[HID + ho];
                    a2 += r * sW2[2*HID + ho];
                    a3 += r * sW2[3*HID + ho];
                }
#pragma unroll
                for (int off = 16; off; off >>= 1) {
                    a0 += __shfl_down_sync(0xffffffffu, a0, off);
                    a1 += __shfl_down_sync(0xffffffffu, a1, off);
                    a2 += __shfl_down_sync(0xffffffffu, a2, off);
                    a3 += __shfl_down_sync(0xffffffffu, a3, off);
                }
                if (lane == 0) {
                    ss[j*4 + 0] = fmaxf(a0 + ba2[0], 0.f);
                    ss[j*4 + 1] = fmaxf(a1 + ba2[1], 0.f);
                    ss[j*4 + 2] = fmaxf(a2 + ba2[2], 0.f);
                    ss[j*4 + 3] = fmaxf(a3 + ba2[3], 0.f);
                }
            }
            __syncthreads();

            if (warp < NHEAD) {
                int k = warp;
                float m = -1e30f;
                for (int j = lane; j <= t; j += 32) m = fmaxf(m, ss[j*4 + k]);
#pragma unroll
                for (int off = 16; off; off >>= 1) m = fmaxf(m, __shfl_xor_sync(0xffffffffu, m, off));
                float s = 0.f;
                for (int j = lane; j <= t; j += 32) s += expf(ss[j*4 + k] - m);
#pragma unroll
                for (int off = 16; off; off >>= 1) s += __shfl_xor_sync(0xffffffffu, s, off);
                float inv = 1.f / s;
                for (int j = lane; j <= t; j += 32) ss[j*4 + k] = expf(ss[j*4 + k] - m) * inv;
            }
            __syncthreads();

            float cv0[NHEAD], cv1[NHEAD];
#pragma unroll
            for (int k = 0; k < NHEAD; k++) { cv0[k] = 0.f; cv1[k] = 0.f; }
            for (int j = 0; j <= t; j++) {
                float w0 = ss[j*4+0], w1 = ss[j*4+1], w2 = ss[j*4+2], w3 = ss[j*4+3];
                float v0 = g_buf[b][j][tid];
                float v1 = g_buf[b][j][tid + 256];
                cv0[0] += w0*v0; cv0[1] += w1*v0; cv0[2] += w2*v0; cv0[3] += w3*v0;
                cv1[0] += w0*v1; cv1[1] += w1*v1; cv1[2] += w2*v1; cv1[3] += w3*v1;
            }
            long zrow = (long)b*SEQT + t;
#pragma unroll
            for (int k = 0; k < NHEAD; k++) {
                bf16 b0 = __float2bfloat16(cv0[k]);
                bf16 b1 = __float2bfloat16(cv1[k]);
                g_xc0b[b][DIN + k*HID + tid]        = b0;
                g_xc0b[b][DIN + k*HID + tid + 256]  = b1;
                g_Zb[zrow][HID + k*HID + tid]       = b0;
                g_Zb[zrow][HID + k*HID + tid + 256] = b1;
            }
            g_xc0b[b][tid] = __float2bfloat16(inputs[((long)b*SEQT + t)*DIN + tid]);
        } else if (bid >= 128) cvt_slot(Wo, t*4 + 1, bid - 128);
        gbar();

        // ===== stage 3: gates0 + cell0 (blocks 0..127, 4 h each, all gates) =====
        if (bid < 128) {
            wmma::fragment<wmma::accumulator,16,16,16,float> c0f, c1f;
            wmma::fill_fragment(c0f, 0.f); wmma::fill_fragment(c1f, 0.f);
#pragma unroll
            for (int ff = 0; ff < F0/8; ff++) {
                int f = warp*(F0/8) + ff;
                const bf16* Ap; int lda;
                if (f < F0A) { Ap = &g_xc0b[0][0] + f*16;              lda = LIN0; }
                else         { Ap = &g_h0prev[par][0][0] + (f-F0A)*16; lda = HID; }
                wmma::fragment<wmma::matrix_a,16,16,16,bf16,wmma::row_major> a0, a1;
                wmma::fragment<wmma::matrix_b,16,16,16,bf16,wmma::col_major> bfr;
                wmma::load_matrix_sync(a0, Ap, lda);
                wmma::load_matrix_sync(a1, Ap + 16*lda, lda);
                wmma::load_matrix_sync(bfr, w0s + f*16, K0);
                wmma::mma_sync(c0f, a0, bfr, c0f);
                wmma::mma_sync(c1f, a1, bfr, c1f);
            }
            wmma::store_matrix_sync(sred + warp*512,       c0f, 16, wmma::mem_row_major);
            wmma::store_matrix_sync(sred + warp*512 + 256, c1f, 16, wmma::mem_row_major);
            __syncthreads();
            if (tid < 128) {
                int b = tid >> 2, hl = tid & 3, h = bid*4 + hl;
                float gv[4];
#pragma unroll
                for (int g = 0; g < 4; g++) {
                    float s = g_bias0p[bid*16 + hl*4 + g];
#pragma unroll
                    for (int w = 0; w < 8; w++) s += sred[w*512 + b*16 + hl*4 + g];
                    gv[g] = s;
                }
                float c  = sigf(gv[1]) * g_c0[b][h] + sigf(gv[0]) * tanhf(gv[2]);
                float hn = sigf(gv[3]) * tanhf(c);
                g_c0[b][h] = c;
                bf16 hb = __float2bfloat16(hn);
                g_h0nb[b][h] = hb;
                g_h0prev[par^1][b][h] = hb;
            }
        } else cvt_slot(Wo, t*4 + 2, bid - 128);
        gbar();

        // ===== stage 4: gates1 + cell1 (blocks 0..127) =====
        if (bid < 128) {
            wmma::fragment<wmma::accumulator,16,16,16,float> c0f, c1f;
            wmma::fill_fragment(c0f, 0.f); wmma::fill_fragment(c1f, 0.f);
#pragma unroll
            for (int ff = 0; ff < F1/8; ff++) {
                int f = warp*(F1/8) + ff;
                const bf16* Ap;
                if (f < 32) Ap = &g_h0nb[0][0] + f*16;
                else        Ap = &g_h1prev[par][0][0] + (f-32)*16;
                wmma::fragment<wmma::matrix_a,16,16,16,bf16,wmma::row_major> a0, a1;
                wmma::fragment<wmma::matrix_b,16,16,16,bf16,wmma::col_major> bfr;
                wmma::load_matrix_sync(a0, Ap, HID);
                wmma::load_matrix_sync(a1, Ap + 16*HID, HID);
                wmma::load_matrix_sync(bfr, w1s + f*16, K1);
                wmma::mma_sync(c0f, a0, bfr, c0f);
                wmma::mma_sync(c1f, a1, bfr, c1f);
            }
            wmma::store_matrix_sync(sred + warp*512,       c0f, 16, wmma::mem_row_major);
            wmma::store_matrix_sync(sred + warp*512 + 256, c1f, 16, wmma::mem_row_major);
            __syncthreads();
            if (tid < 128) {
                int b = tid >> 2, hl = tid & 3, h = bid*4 + hl;
                float gv[4];
#pragma unroll
                for (int g = 0; g < 4; g++) {
                    float s = g_bias1p[bid*16 + hl*4 + g];
#pragma unroll
                    for (int w = 0; w < 8; w++) s += sred[w*512 + b*16 + hl*4 + g];
                    gv[g] = s;
                }
                float c  = sigf(gv[1]) * g_c1[b][h] + sigf(gv[0]) * tanhf(gv[2]);
                float hn = sigf(gv[3]) * tanhf(c);
                g_c1[b][h] = c;
                g_buf[b][t+1][h] = hn;
                bf16 hb = __float2bfloat16(hn);
                g_h1b[b][h] = hb;
                g_h1prev[par^1][b][h] = hb;
                g_Zb[(long)b*SEQT + t][h] = hb;
            }
        } else cvt_slot(Wo, t*4 + 3, bid - 128);
        gbar();
    }
}

// ---------------- big output GEMM: out = Zb(3072x2560) @ Wob(32000x2560)^T ----
constexpr int BM = 128, BN = 128, BK = 64;
constexpr int LDS = BK + 8;  // 72
constexpr int SMEM_GEMM = 2 * (BM*LDS + BN*LDS) * (int)sizeof(bf16);  // 73728

__device__ __forceinline__ void cpa16(void* sdst, const void* gsrc) {
    unsigned s = (unsigned)__cvta_generic_to_shared(sdst);
    asm volatile("cp.async.cg.shared.global [%0], [%1], 16;\n" :: "r"(s), "l"(gsrc));
}

__global__ void __launch_bounds__(256, 2) k_bigGemm(float* __restrict__ out) {
    extern __shared__ bf16 dyn[];
    bf16 (*sA)[BM][LDS] = (bf16 (*)[BM][LDS])dyn;
    bf16 (*sB)[BN][LDS] = (bf16 (*)[BN][LDS])(dyn + 2*BM*LDS);
    int m0 = blockIdx.x * BM;
    int n0 = blockIdx.y * BN;
    int tid = threadIdx.x;
    int warp = tid >> 5;
    int wm = warp & 3;
    int wn = warp >> 2;

    wmma::fragment<wmma::accumulator, 16, 16, 16, float> acc[2][4];
#pragma unroll
    for (int i = 0; i < 2; i++)
#pragma unroll
        for (int j = 0; j < 4; j++) wmma::fill_fragment(acc[i][j], 0.f);

    auto load_tile = [&](int buf, int k0) {
#pragma unroll
        for (int r = 0; r < 4; r++) {
            int idx = tid + r * 256;
            int row = idx >> 3, c = (idx & 7) * 8;
            cpa16(&sA[buf][row][c], &g_Zb[m0 + row][k0 + c]);
            cpa16(&sB[buf][row][c], &g_Wob[n0 + row][k0 + c]);
        }
        asm volatile("cp.async.commit_group;\n");
    };

    load_tile(0, 0);
    int buf = 0;
    for (int k0 = 0; k0 < ZK; k0 += BK) {
        if (k0 + BK < ZK) {
            load_tile(buf ^ 1, k0 + BK);
            asm volatile("cp.async.wait_group 1;\n");
        } else {
            asm volatile("cp.async.wait_group 0;\n");
        }
        __syncthreads();
#pragma unroll
        for (int kf = 0; kf < BK/16; kf++) {
            wmma::fragment<wmma::matrix_a, 16,16,16, bf16, wmma::row_major> af[2];
            wmma::fragment<wmma::matrix_b, 16,16,16, bf16, wmma::col_major> bf_[4];
#pragma unroll
            for (int i = 0; i < 2; i++)
                wmma::load_matrix_sync(af[i], &sA[buf][wm*32 + i*16][kf*16], LDS);
#pragma unroll
            for (int j = 0; j < 4; j++)
                wmma::load_matrix_sync(bf_[j], &sB[buf][wn*64 + j*16][kf*16], LDS);
#pragma unroll
            for (int i = 0; i < 2; i++)
#pragma unroll
                for (int j = 0; j < 4; j++)
                    wmma::mma_sync(acc[i][j], af[i], bf_[j], acc[i][j]);
        }
        __syncthreads();
        buf ^= 1;
    }
#pragma unroll
    for (int i = 0; i < 2; i++)
#pragma unroll
        for (int j = 0; j < 4; j++)
            wmma::store_matrix_sync(&out[(long)(m0 + wm*32 + i*16) * VOCAB + n0 + wn*64 + j*16],
                                    acc[i][j], VOCAB, wmma::mem_row_major);
}

// ---------------- online log-softmax (2 passes) ----------------
__global__ void k_logsoftmax(float* __restrict__ out, const float* __restrict__ bo) {
    long row = blockIdx.x;
    float* p = out + row * (long)VOCAB;
    int tid = threadIdx.x;
    int warp = tid >> 5, lane = tid & 31;
    __shared__ float rm[8], rs[8], bc;

    float m = -1e30f, s = 0.f;
    for (int j = tid; j < VOCAB; j += 256) {
        float v = p[j] + bo[j];
        float nm = fmaxf(m, v);
        s = s * __expf(m - nm) + __expf(v - nm);
        m = nm;
    }
#pragma unroll
    for (int off = 16; off; off >>= 1) {
        float om = __shfl_xor_sync(0xffffffffu, m, off);
        float os = __shfl_xor_sync(0xffffffffu, s, off);
        float nm = fmaxf(m, om);
        s = s * __expf(m - nm) + os * __expf(om - nm);
        m = nm;
    }
    if (lane == 0) { rm[warp] = m; rs[warp] = s; }
    __syncthreads();
    if (tid == 0) {
        float M = rm[0], S = rs[0];
#pragma unroll
        for (int i = 1; i < 8; i++) {
            float nm = fmaxf(M, rm[i]);
            S = S * __expf(M - nm) + rs[i] * __expf(rm[i] - nm);
            M = nm;
        }
        bc = M + logf(S);
    }
    __syncthreads();
    float ls = bc;
    for (int j = tid; j < VOCAB; j += 256) p[j] = p[j] + bo[j] - ls;
}

// ---------------- host launcher ----------------
extern "C" void kernel_launch(void* const* d_in, const int* in_sizes, int n_in,
                              void* d_out, int out_size) {
    const float* inputs = (const float*)d_in[0];
    const float* W_ih0  = (const float*)d_in[1];
    const float* W_hh0  = (const float*)d_in[2];
    const float* b_ih0  = (const float*)d_in[3];
    const float* b_hh0  = (const float*)d_in[4];
    const float* W_ih1  = (const float*)d_in[5];
    const float* W_hh1  = (const float*)d_in[6];
    const float* b_ih1  = (const float*)d_in[7];
    const float* b_hh1  = (const float*)d_in[8];
    const float* Wa1    = (const float*)d_in[9];
    const float* ba1    = (const float*)d_in[10];
    const float* Wa2    = (const float*)d_in[11];
    const float* ba2    = (const float*)d_in[12];
    const float* Wo     = (const float*)d_in[13];
    const float* bo     = (const float*)d_in[14];
    float* out = (float*)d_out;

    cudaFuncSetAttribute(k_recur,   cudaFuncAttributeMaxDynamicSharedMemorySize, SMEM_RECUR);
    cudaFuncSetAttribute(k_bigGemm, cudaFuncAttributeMaxDynamicSharedMemorySize, SMEM_GEMM);

    k_setup<<<4096, 256>>>(W_ih0, W_hh0, b_ih0, b_hh0, W_ih1, W_hh1, b_ih1, b_hh1, Wa1);
    k_recur<<<GRID, NTH, SMEM_RECUR>>>(inputs, Wa2, ba1, ba2, Wo);
    k_bigGemm<<<dim3((BATCH*SEQT)/BM, VOCAB/BN), 256, SMEM_GEMM>>>(out);
    k_logsoftmax<<<BATCH*SEQT, 256>>>(out, bo);
}

// round 10
// speedup vs baseline: 1.0116x; 1.0116x over previous
#include <cuda_runtime.h>
#include <cuda_bf16.h>
#include <mma.h>
using namespace nvcuda;
typedef __nv_bfloat16 bf16;

constexpr int BATCH = 32;
constexpr int SEQT  = 96;
constexpr int DIN   = 256;
constexpr int HID   = 512;
constexpr int NHEAD = 4;
constexpr int VOCAB = 32000;
constexpr int NG    = 4 * HID;           // 2048
constexpr int LIN0  = DIN + NHEAD*HID;   // 2304  (x_t | cvec)
constexpr int K0    = LIN0 + HID;        // 2816  (+ h0prev)
constexpr int K1    = 2 * HID;           // 1024  (h0n | h1prev)
constexpr int ZK    = (1 + NHEAD) * HID; // 2560

constexpr int GRID = 148;
constexpr int NTH  = 256;
constexpr int F0   = K0 / 16;    // 176 frags (22/warp)
constexpr int F0A  = LIN0 / 16;  // 144 frags from xc part
constexpr int F1   = K1 / 16;    // 64 frags (8/warp)
constexpr int FQ   = HID / 16;   // 32 frags (4/warp)

// smem layout for k_recur (dynamic)
constexpr int W0S_OFF = 0;                       // 16 x 2816 bf16 = 90112
constexpr int W1S_OFF = 90112;                   // 16 x 1024 bf16 = 32768
constexpr int WQS_OFF = 122880;                  // 16 x 512  bf16 = 16384
constexpr int RED_OFF = 139264;                  // 4096 floats = 16384
constexpr int SMEM_RECUR = 155648;

// Wo conversion hidden in idle blocks: 20 blocks x 384 slots
constexpr long CVT_N = (long)VOCAB * ZK / 2;     // 40,960,000 bf16x2
constexpr long CVT_CHUNK = 5376;                 // 20*384*5376 >= CVT_N

// ---------------- device scratch ----------------
__device__ __align__(256) float g_buf[BATCH][SEQT+1][HID];
__device__ __align__(256) float g_P  [BATCH][SEQT+1][HID];
__device__ __align__(256) float g_q  [BATCH][HID];
__device__ __align__(256) float g_c0[BATCH][HID], g_c1[BATCH][HID];
__device__ __align__(256) float g_bias0p[NG], g_bias1p[NG];
__device__ __align__(256) bf16 g_h1b[BATCH][HID];       // qp input
__device__ __align__(256) bf16 g_xc0b[BATCH][LIN0];     // [x_t | cvec]
__device__ __align__(256) bf16 g_h0prev[2][BATCH][HID]; // parity double-buffer
__device__ __align__(256) bf16 g_h0nb[BATCH][HID];      // layer-1 input (this step)
__device__ __align__(256) bf16 g_h1prev[2][BATCH][HID];
__device__ __align__(256) bf16 g_W0p[NG][K0];           // gate-interleaved (po = h*4+g)
__device__ __align__(256) bf16 g_W1p[NG][K1];
__device__ __align__(256) bf16 g_Wqpb[2*HID][HID];
__device__ __align__(256) bf16 g_Zb [BATCH*SEQT][ZK];
__device__ __align__(256) bf16 g_Wob[VOCAB][ZK];
__device__ unsigned g_barCnt;
__device__ unsigned g_barPhase;

__device__ __forceinline__ float sigf(float x) { return 1.0f / (1.0f + expf(-x)); }

// ---------------- grid barrier (all GRID blocks resident) ----------------
__device__ __forceinline__ void gbar() {
    __syncthreads();
    if (threadIdx.x == 0) {
        __threadfence();
        unsigned old = atomicAdd(&g_barCnt, 1u);
        unsigned target = old / GRID + 1u;
        if (old % GRID == GRID - 1u) {
            atomicExch(&g_barPhase, target);
        } else {
            const volatile unsigned* vp = &g_barPhase;
            while (*vp < target) { }
        }
        __threadfence();
    }
    __syncthreads();
}

// ---------------- setup: pack (gate-interleaved) + convert weights, zero state ----
__global__ void k_setup(const float* __restrict__ W_ih0, const float* __restrict__ W_hh0,
                        const float* __restrict__ b_ih0, const float* __restrict__ b_hh0,
                        const float* __restrict__ W_ih1, const float* __restrict__ W_hh1,
                        const float* __restrict__ b_ih1, const float* __restrict__ b_hh1,
                        const float* __restrict__ Wa1) {
    if (blockIdx.x == 0 && threadIdx.x == 0) { g_barCnt = 0u; g_barPhase = 0u; }
    long i      = (long)blockIdx.x * blockDim.x + threadIdx.x;
    long stride = (long)gridDim.x * blockDim.x;
    const long n0 = (long)NG * K0;            // W0p
    const long n1 = n0 + (long)NG * K1;       // W1p
    const long n2 = n1 + (long)2*HID*HID;     // Wqpb
    const long n3 = n2 + NG;                  // bias0p
    const long n4 = n3 + NG;                  // bias1p
    const long n5 = n4 + (long)3*BATCH*HID;   // fp32 zeros: c0,c1,buf[.,0,.]
    const long n6 = n5 + (long)5*BATCH*HID;   // bf16 zeros: h1b, h0prev x2, h1prev x2
    for (long idx = i; idx < n6; idx += stride) {
        if (idx < n0) {
            long po = idx / K0, k = idx % K0;
            long h = po >> 2, gt = po & 3;
            long orig = gt * HID + h;
            float v = (k < LIN0) ? W_ih0[orig*LIN0 + k] : W_hh0[orig*HID + (k - LIN0)];
            g_W0p[po][k] = __float2bfloat16(v);
        } else if (idx < n1) {
            long r = idx - n0; long po = r / K1, k = r % K1;
            long h = po >> 2, gt = po & 3;
            long orig = gt * HID + h;
            float v = (k < HID) ? W_ih1[orig*HID + k] : W_hh1[orig*HID + (k - HID)];
            g_W1p[po][k] = __float2bfloat16(v);
        } else if (idx < n2) {
            long r = idx - n1; long n = r / HID, k = r % HID;
            float v = (n < HID) ? Wa1[n*(2*HID) + k] : Wa1[(n-HID)*(2*HID) + HID + k];
            g_Wqpb[n][k] = __float2bfloat16(v);
        } else if (idx < n3) {
            long po = idx - n2;
            long h = po >> 2, gt = po & 3;
            long orig = gt * HID + h;
            g_bias0p[po] = b_ih0[orig] + b_hh0[orig];
        } else if (idx < n4) {
            long po = idx - n3;
            long h = po >> 2, gt = po & 3;
            long orig = gt * HID + h;
            g_bias1p[po] = b_ih1[orig] + b_hh1[orig];
        } else if (idx < n5) {
            long r = idx - n4; int which = (int)(r / (BATCH*HID));
            long o = r % (BATCH*HID); long b = o / HID, h = o % HID;
            if (which == 0) g_c0[b][h] = 0.f;
            else if (which == 1) g_c1[b][h] = 0.f;
            else g_buf[b][0][h] = 0.f;
        } else {
            long r = idx - n5; int which = (int)(r / (BATCH*HID));
            long o = r % (BATCH*HID); long b = o / HID, h = o % HID;
            bf16 z = __float2bfloat16(0.f);
            switch (which) {
                case 0: g_h1b[b][h] = z; break;
                case 1: g_h0prev[0][b][h] = z; break;
                case 2: g_h0prev[1][b][h] = z; break;
                case 3: g_h1prev[0][b][h] = z; break;
                default: g_h1prev[1][b][h] = z; break;
            }
        }
    }
}

// idle blocks convert Wo fp32 -> bf16, one chunk per barrier slot
__device__ __forceinline__ void cvt_slot(const float* __restrict__ Wo, int slot, int cb) {
    long base = ((long)slot * 20 + cb) * CVT_CHUNK;
    const float2* src = (const float2*)Wo;
    __nv_bfloat162* dst = (__nv_bfloat162*)&g_Wob[0][0];
    long end = base + CVT_CHUNK; if (end > CVT_N) end = CVT_N;
    for (long i = base + threadIdx.x; i < end; i += NTH)
        dst[i] = __float22bfloat162_rn(src[i]);
}

// ---------------- persistent recurrence ----------------
__global__ void __launch_bounds__(NTH) k_recur(const float* __restrict__ inputs,
                                               const float* __restrict__ Wa2,
                                               const float* __restrict__ ba1,
                                               const float* __restrict__ ba2,
                                               const float* __restrict__ Wo) {
    extern __shared__ char smem[];
    bf16*  w0s  = (bf16*)(smem + W0S_OFF);
    bf16*  w1s  = (bf16*)(smem + W1S_OFF);
    bf16*  wqs  = (bf16*)(smem + WQS_OFF);
    float* sred = (float*)(smem + RED_OFF);   // 4096 floats; attn aliases this

    const int bid = blockIdx.x, tid = threadIdx.x;
    const int warp = tid >> 5, lane = tid & 31;

    // ---- preload this block's weight slices into smem (once) ----
    if (bid < 128) {
        const uint4* s0 = (const uint4*)&g_W0p[bid*16][0];
        uint4* d0 = (uint4*)w0s;
        for (int i = tid; i < 16*K0/8; i += NTH) d0[i] = s0[i];
        const uint4* s1 = (const uint4*)&g_W1p[bid*16][0];
        uint4* d1 = (uint4*)w1s;
        for (int i = tid; i < 16*K1/8; i += NTH) d1[i] = s1[i];
        if (bid < 64) {
            const uint4* sq = (const uint4*)&g_Wqpb[bid*16][0];
            uint4* dq = (uint4*)wqs;
            for (int i = tid; i < 16*HID/8; i += NTH) dq[i] = sq[i];
        }
    }
    __syncthreads();

    for (int t = 0; t < SEQT; t++) {
        const int par = t & 1;

        // ===== stage 1: qp = h1b @ Wqpb^T (blocks 0..63, 16 cols each) =====
        if (bid < 64) {
            wmma::fragment<wmma::accumulator,16,16,16,float> c0f, c1f;
            wmma::fill_fragment(c0f, 0.f); wmma::fill_fragment(c1f, 0.f);
#pragma unroll
            for (int ff = 0; ff < FQ/8; ff++) {
                int f = warp*(FQ/8) + ff;
                wmma::fragment<wmma::matrix_a,16,16,16,bf16,wmma::row_major> a0, a1;
                wmma::fragment<wmma::matrix_b,16,16,16,bf16,wmma::col_major> bfr;
                const bf16* Ap = &g_h1b[0][0] + f*16;
                wmma::load_matrix_sync(a0, Ap, HID);
                wmma::load_matrix_sync(a1, Ap + 16*HID, HID);
                wmma::load_matrix_sync(bfr, wqs + f*16, HID);
                wmma::mma_sync(c0f, a0, bfr, c0f);
                wmma::mma_sync(c1f, a1, bfr, c1f);
            }
            wmma::store_matrix_sync(sred + warp*512,       c0f, 16, wmma::mem_row_major);
            wmma::store_matrix_sync(sred + warp*512 + 256, c1f, 16, wmma::mem_row_major);
            __syncthreads();
            int n0 = bid * 16;
            for (int e = tid; e < 512; e += NTH) {
                float s = 0.f;
#pragma unroll
                for (int w = 0; w < 8; w++) s += sred[w*512 + e];
                int b = e >> 4, n = n0 + (e & 15);
                if (n < HID) g_q[b][n] = s + ba1[n];
                else         g_P[b][t][n - HID] = s;
            }
        } else if (bid >= 128) cvt_slot(Wo, t*4 + 0, bid - 128);
        gbar();

        // ===== stage 2: attention (blocks 0..31 = batch) =====
        if (bid < BATCH) {
            int b = bid;
            float* sq  = sred;          // 512
            float* sW2 = sred + 512;    // 2048
            float* ss  = sred + 2560;   // up to 384
            for (int ho = tid; ho < HID; ho += NTH) sq[ho] = g_q[b][ho];
            for (int idx = tid; idx < NHEAD*HID; idx += NTH) sW2[idx] = Wa2[idx];
            __syncthreads();

            for (int j = warp; j <= t; j += 8) {
                float a0 = 0.f, a1 = 0.f, a2 = 0.f, a3 = 0.f;
                const float* Pj = &g_P[b][j][0];
                for (int ho = lane; ho < HID; ho += 32) {
                    float r = fmaxf(sq[ho] + Pj[ho], 0.f);
                    a0 += r * sW2[ho];
                    a1 += r * sW2[HID + ho];
                    a2 += r * sW2[2*HID + ho];
                    a3 += r * sW2[3*HID + ho];
                }
#pragma unroll
                for (int off = 16; off; off >>= 1) {
                    a0 += __shfl_down_sync(0xffffffffu, a0, off);
                    a1 += __shfl_down_sync(0xffffffffu, a1, off);
                    a2 += __shfl_down_sync(0xffffffffu, a2, off);
                    a3 += __shfl_down_sync(0xffffffffu, a3, off);
                }
                if (lane == 0) {
                    ss[j*4 + 0] = fmaxf(a0 + ba2[0], 0.f);
                    ss[j*4 + 1] = fmaxf(a1 + ba2[1], 0.f);
                    ss[j*4 + 2] = fmaxf(a2 + ba2[2], 0.f);
                    ss[j*4 + 3] = fmaxf(a3 + ba2[3], 0.f);
                }
            }
            __syncthreads();

            if (warp < NHEAD) {
                int k = warp;
                float m = -1e30f;
                for (int j = lane; j <= t; j += 32) m = fmaxf(m, ss[j*4 + k]);
#pragma unroll
                for (int off = 16; off; off >>= 1) m = fmaxf(m, __shfl_xor_sync(0xffffffffu, m, off));
                float s = 0.f;
                for (int j = lane; j <= t; j += 32) s += expf(ss[j*4 + k] - m);
#pragma unroll
                for (int off = 16; off; off >>= 1) s += __shfl_xor_sync(0xffffffffu, s, off);
                float inv = 1.f / s;
                for (int j = lane; j <= t; j += 32) ss[j*4 + k] = expf(ss[j*4 + k] - m) * inv;
            }
            __syncthreads();

            float cv0[NHEAD], cv1[NHEAD];
#pragma unroll
            for (int k = 0; k < NHEAD; k++) { cv0[k] = 0.f; cv1[k] = 0.f; }
            for (int j = 0; j <= t; j++) {
                float w0 = ss[j*4+0], w1 = ss[j*4+1], w2 = ss[j*4+2], w3 = ss[j*4+3];
                float v0 = g_buf[b][j][tid];
                float v1 = g_buf[b][j][tid + 256];
                cv0[0] += w0*v0; cv0[1] += w1*v0; cv0[2] += w2*v0; cv0[3] += w3*v0;
                cv1[0] += w0*v1; cv1[1] += w1*v1; cv1[2] += w2*v1; cv1[3] += w3*v1;
            }
            long zrow = (long)b*SEQT + t;
#pragma unroll
            for (int k = 0; k < NHEAD; k++) {
                bf16 b0 = __float2bfloat16(cv0[k]);
                bf16 b1 = __float2bfloat16(cv1[k]);
                g_xc0b[b][DIN + k*HID + tid]        = b0;
                g_xc0b[b][DIN + k*HID + tid + 256]  = b1;
                g_Zb[zrow][HID + k*HID + tid]       = b0;
                g_Zb[zrow][HID + k*HID + tid + 256] = b1;
            }
            g_xc0b[b][tid] = __float2bfloat16(inputs[((long)b*SEQT + t)*DIN + tid]);
        } else if (bid >= 128) cvt_slot(Wo, t*4 + 1, bid - 128);
        gbar();

        // ===== stage 3: gates0 + cell0 (blocks 0..127, 4 h each, all gates) =====
        if (bid < 128) {
            wmma::fragment<wmma::accumulator,16,16,16,float> c0f, c1f;
            wmma::fill_fragment(c0f, 0.f); wmma::fill_fragment(c1f, 0.f);
#pragma unroll
            for (int ff = 0; ff < F0/8; ff++) {
                int f = warp*(F0/8) + ff;
                const bf16* Ap; int lda;
                if (f < F0A) { Ap = &g_xc0b[0][0] + f*16;              lda = LIN0; }
                else         { Ap = &g_h0prev[par][0][0] + (f-F0A)*16; lda = HID; }
                wmma::fragment<wmma::matrix_a,16,16,16,bf16,wmma::row_major> a0, a1;
                wmma::fragment<wmma::matrix_b,16,16,16,bf16,wmma::col_major> bfr;
                wmma::load_matrix_sync(a0, Ap, lda);
                wmma::load_matrix_sync(a1, Ap + 16*lda, lda);
                wmma::load_matrix_sync(bfr, w0s + f*16, K0);
                wmma::mma_sync(c0f, a0, bfr, c0f);
                wmma::mma_sync(c1f, a1, bfr, c1f);
            }
            wmma::store_matrix_sync(sred + warp*512,       c0f, 16, wmma::mem_row_major);
            wmma::store_matrix_sync(sred + warp*512 + 256, c1f, 16, wmma::mem_row_major);
            __syncthreads();
            if (tid < 128) {
                int b = tid >> 2, hl = tid & 3, h = bid*4 + hl;
                float gv[4];
#pragma unroll
                for (int g = 0; g < 4; g++) {
                    float s = g_bias0p[bid*16 + hl*4 + g];
#pragma unroll
                    for (int w = 0; w < 8; w++) s += sred[w*512 + b*16 + hl*4 + g];
                    gv[g] = s;
                }
                float c  = sigf(gv[1]) * g_c0[b][h] + sigf(gv[0]) * tanhf(gv[2]);
                float hn = sigf(gv[3]) * tanhf(c);
                g_c0[b][h] = c;
                bf16 hb = __float2bfloat16(hn);
                g_h0nb[b][h] = hb;
                g_h0prev[par^1][b][h] = hb;
            }
        } else cvt_slot(Wo, t*4 + 2, bid - 128);
        gbar();

        // ===== stage 4: gates1 + cell1 (blocks 0..127) =====
        if (bid < 128) {
            wmma::fragment<wmma::accumulator,16,16,16,float> c0f, c1f;
            wmma::fill_fragment(c0f, 0.f); wmma::fill_fragment(c1f, 0.f);
#pragma unroll
            for (int ff = 0; ff < F1/8; ff++) {
                int f = warp*(F1/8) + ff;
                const bf16* Ap;
                if (f < 32) Ap = &g_h0nb[0][0] + f*16;
                else        Ap = &g_h1prev[par][0][0] + (f-32)*16;
                wmma::fragment<wmma::matrix_a,16,16,16,bf16,wmma::row_major> a0, a1;
                wmma::fragment<wmma::matrix_b,16,16,16,bf16,wmma::col_major> bfr;
                wmma::load_matrix_sync(a0, Ap, HID);
                wmma::load_matrix_sync(a1, Ap + 16*HID, HID);
                wmma::load_matrix_sync(bfr, w1s + f*16, K1);
                wmma::mma_sync(c0f, a0, bfr, c0f);
                wmma::mma_sync(c1f, a1, bfr, c1f);
            }
            wmma::store_matrix_sync(sred + warp*512,       c0f, 16, wmma::mem_row_major);
            wmma::store_matrix_sync(sred + warp*512 + 256, c1f, 16, wmma::mem_row_major);
            __syncthreads();
            if (tid < 128) {
                int b = tid >> 2, hl = tid & 3, h = bid*4 + hl;
                float gv[4];
#pragma unroll
                for (int g = 0; g < 4; g++) {
                    float s = g_bias1p[bid*16 + hl*4 + g];
#pragma unroll
                    for (int w = 0; w < 8; w++) s += sred[w*512 + b*16 + hl*4 + g];
                    gv[g] = s;
                }
                float c  = sigf(gv[1]) * g_c1[b][h] + sigf(gv[0]) * tanhf(gv[2]);
                float hn = sigf(gv[3]) * tanhf(c);
                g_c1[b][h] = c;
                g_buf[b][t+1][h] = hn;
                bf16 hb = __float2bfloat16(hn);
                g_h1b[b][h] = hb;
                g_h1prev[par^1][b][h] = hb;
                g_Zb[(long)b*SEQT + t][h] = hb;
            }
        } else cvt_slot(Wo, t*4 + 3, bid - 128);
        gbar();
    }
}

// ---------------- big output GEMM: out = Zb(3072x2560) @ Wob(32000x2560)^T ----
constexpr int BM = 128, BN = 128, BK = 64;
constexpr int LDS = BK + 8;  // 72
constexpr int SMEM_GEMM = 2 * (BM*LDS + BN*LDS) * (int)sizeof(bf16);  // 73728

__device__ __forceinline__ void cpa16(void* sdst, const void* gsrc) {
    unsigned s = (unsigned)__cvta_generic_to_shared(sdst);
    asm volatile("cp.async.cg.shared.global [%0], [%1], 16;\n" :: "r"(s), "l"(gsrc));
}

__global__ void __launch_bounds__(256, 2) k_bigGemm(float* __restrict__ out) {
    extern __shared__ bf16 dyn[];
    bf16 (*sA)[BM][LDS] = (bf16 (*)[BM][LDS])dyn;
    bf16 (*sB)[BN][LDS] = (bf16 (*)[BN][LDS])(dyn + 2*BM*LDS);
    int m0 = blockIdx.x * BM;
    int n0 = blockIdx.y * BN;
    int tid = threadIdx.x;
    int warp = tid >> 5;
    int wm = warp & 3;
    int wn = warp >> 2;

    wmma::fragment<wmma::accumulator, 16, 16, 16, float> acc[2][4];
#pragma unroll
    for (int i = 0; i < 2; i++)
#pragma unroll
        for (int j = 0; j < 4; j++) wmma::fill_fragment(acc[i][j], 0.f);

    auto load_tile = [&](int buf, int k0) {
#pragma unroll
        for (int r = 0; r < 4; r++) {
            int idx = tid + r * 256;
            int row = idx >> 3, c = (idx & 7) * 8;
            cpa16(&sA[buf][row][c], &g_Zb[m0 + row][k0 + c]);
            cpa16(&sB[buf][row][c], &g_Wob[n0 + row][k0 + c]);
        }
        asm volatile("cp.async.commit_group;\n");
    };

    load_tile(0, 0);
    int buf = 0;
    for (int k0 = 0; k0 < ZK; k0 += BK) {
        if (k0 + BK < ZK) {
            load_tile(buf ^ 1, k0 + BK);
            asm volatile("cp.async.wait_group 1;\n");
        } else {
            asm volatile("cp.async.wait_group 0;\n");
        }
        __syncthreads();
#pragma unroll
        for (int kf = 0; kf < BK/16; kf++) {
            wmma::fragment<wmma::matrix_a, 16,16,16, bf16, wmma::row_major> af[2];
            wmma::fragment<wmma::matrix_b, 16,16,16, bf16, wmma::col_major> bf_[4];
#pragma unroll
            for (int i = 0; i < 2; i++)
                wmma::load_matrix_sync(af[i], &sA[buf][wm*32 + i*16][kf*16], LDS);
#pragma unroll
            for (int j = 0; j < 4; j++)
                wmma::load_matrix_sync(bf_[j], &sB[buf][wn*64 + j*16][kf*16], LDS);
#pragma unroll
            for (int i = 0; i < 2; i++)
#pragma unroll
                for (int j = 0; j < 4; j++)
                    wmma::mma_sync(acc[i][j], af[i], bf_[j], acc[i][j]);
        }
        __syncthreads();
        buf ^= 1;
    }
#pragma unroll
    for (int i = 0; i < 2; i++)
#pragma unroll
        for (int j = 0; j < 4; j++)
            wmma::store_matrix_sync(&out[(long)(m0 + wm*32 + i*16) * VOCAB + n0 + wn*64 + j*16],
                                    acc[i][j], VOCAB, wmma::mem_row_major);
}

// ---------------- online log-softmax (2 passes) ----------------
__global__ void k_logsoftmax(float* __restrict__ out, const float* __restrict__ bo) {
    long row = blockIdx.x;
    float* p = out + row * (long)VOCAB;
    int tid = threadIdx.x;
    int warp = tid >> 5, lane = tid & 31;
    __shared__ float rm[8], rs[8], bc;

    float m = -1e30f, s = 0.f;
    for (int j = tid; j < VOCAB; j += 256) {
        float v = p[j] + bo[j];
        float nm = fmaxf(m, v);
        s = s * __expf(m - nm) + __expf(v - nm);
        m = nm;
    }
#pragma unroll
    for (int off = 16; off; off >>= 1) {
        float om = __shfl_xor_sync(0xffffffffu, m, off);
        float os = __shfl_xor_sync(0xffffffffu, s, off);
        float nm = fmaxf(m, om);
        s = s * __expf(m - nm) + os * __expf(om - nm);
        m = nm;
    }
    if (lane == 0) { rm[warp] = m; rs[warp] = s; }
    __syncthreads();
    if (tid == 0) {
        float M = rm[0], S = rs[0];
#pragma unroll
        for (int i = 1; i < 8; i++) {
            float nm = fmaxf(M, rm[i]);
            S = S * __expf(M - nm) + rs[i] * __expf(rm[i] - nm);
            M = nm;
        }
        bc = M + logf(S);
    }
    __syncthreads();
    float ls = bc;
    for (int j = tid; j < VOCAB; j += 256) p[j] = p[j] + bo[j] - ls;
}

// ---------------- host launcher ----------------
extern "C" void kernel_launch(void* const* d_in, const int* in_sizes, int n_in,
                              void* d_out, int out_size) {
    const float* inputs = (const float*)d_in[0];
    const float* W_ih0  = (const float*)d_in[1];
    const float* W_hh0  = (const float*)d_in[2];
    const float* b_ih0  = (const float*)d_in[3];
    const float* b_hh0  = (const float*)d_in[4];
    const float* W_ih1  = (const float*)d_in[5];
    const float* W_hh1  = (const float*)d_in[6];
    const float* b_ih1  = (const float*)d_in[7];
    const float* b_hh1  = (const float*)d_in[8];
    const float* Wa1    = (const float*)d_in[9];
    const float* ba1    = (const float*)d_in[10];
    const float* Wa2    = (const float*)d_in[11];
    const float* ba2    = (const float*)d_in[12];
    const float* Wo     = (const float*)d_in[13];
    const float* bo     = (const float*)d_in[14];
    float* out = (float*)d_out;

    cudaFuncSetAttribute(k_recur,   cudaFuncAttributeMaxDynamicSharedMemorySize, SMEM_RECUR);
    cudaFuncSetAttribute(k_bigGemm, cudaFuncAttributeMaxDynamicSharedMemorySize, SMEM_GEMM);

    k_setup<<<4096, 256>>>(W_ih0, W_hh0, b_ih0, b_hh0, W_ih1, W_hh1, b_ih1, b_hh1, Wa1);
    k_recur<<<GRID, NTH, SMEM_RECUR>>>(inputs, Wa2, ba1, ba2, Wo);
    k_bigGemm<<<dim3((BATCH*SEQT)/BM, VOCAB/BN), 256, SMEM_GEMM>>>(out);
    k_logsoftmax<<<BATCH*SEQT, 256>>>(out, bo);
}